// round 6
// baseline (speedup 1.0000x reference)
#include <cuda_runtime.h>
#include <cstdint>

#define BATCH    16384
#define IN_DIM   512
#define NH       128
#define NO       256
#define NNODES   (NH + NO)         // 384
#define SRCW     (IN_DIM + NH)     // 640
#define TB       32                // batch rows per tile (1 float per lane)
#define NTHREADS 1024
#define NWARPS   32
#define MAXE     16384

// Persistent scratch rebuilt by prep each launch (deterministic).
__device__ int2 g_edges[MAXE];       // packed (q, w), sorted by (node, act)
__device__ int4 g_infoA[NNODES];     // per schedule slot: e0,e1,e2,e3
__device__ int2 g_infoB[NNODES];     // per schedule slot: e4, node_id

__device__ __forceinline__ float tanha(float z) {
    float r;
    asm("tanh.approx.f32 %0, %1;" : "=f"(r) : "f"(z));
    return r;
}

// ================= Fused prep: histogram + scan + scatter + LPT (1 block) =========
__global__ void __launch_bounds__(1024)
prep_all(const int* __restrict__ rows_h, const int* __restrict__ cols_h,
         const int* __restrict__ acts_h, const float* __restrict__ wh,
         const int* __restrict__ rows_o, const int* __restrict__ cols_o,
         const int* __restrict__ acts_o, const float* __restrict__ wo,
         int Eh, int Eo)
{
    __shared__ int cnt[NNODES * 4];
    __shared__ int off[NNODES * 4 + 1];
    __shared__ int wsum[32];

    const int tid = threadIdx.x, lane = tid & 31, wid = tid >> 5;

    for (int i = tid; i < NNODES * 4; i += 1024) cnt[i] = 0;
    __syncthreads();

    for (int e = tid; e < Eh; e += 1024)
        atomicAdd(&cnt[rows_h[e] * 4 + acts_h[e] - 1], 1);
    for (int e = tid; e < Eo; e += 1024)
        atomicAdd(&cnt[(NH + rows_o[e]) * 4 + acts_o[e] - 1], 1);
    __syncthreads();

    if (lane == 0) {
        const int base = wid * 48;
        int run = 0;
        for (int i = 0; i < 48; ++i) { off[base + i] = run; run += cnt[base + i]; }
        wsum[wid] = run;
    }
    __syncthreads();
    if (wid == 0) {
        const int v = wsum[lane];
        int ex = v;
        #pragma unroll
        for (int d = 1; d < 32; d <<= 1) {
            const int t = __shfl_up_sync(0xffffffffu, ex, d);
            if (lane >= d) ex += t;
        }
        ex -= v;
        wsum[lane] = ex;
        if (lane == 31) off[NNODES * 4] = ex + v;
    }
    __syncthreads();
    for (int i = tid; i < NNODES * 4; i += 1024) off[i] += wsum[i / 48];
    __syncthreads();

    for (int n = wid; n < NNODES; n += 32) {
        const bool hid = n < NH;
        const int* cols = hid ? cols_h : cols_o;
        const int* acts = hid ? acts_h : acts_o;
        const float* wp = hid ? wh : wo;
        const int sub = hid ? 0 : Eh;
        const int s = off[n * 4] - sub;
        const int e = off[(n + 1) * 4] - sub;
        int d0 = off[n * 4], d1 = off[n * 4 + 1], d2 = off[n * 4 + 2], d3 = off[n * 4 + 3];
        for (int c = s; c < e; c += 32) {
            const int idx = c + lane;
            const bool v = idx < e;
            const int act = v ? acts[idx] : 0;
            const int col = v ? cols[idx] : 0;
            const float w = v ? wp[idx] : 0.f;
            // byte addr word: q = col*128 | ((col&31)<<2); lane addr = q ^ (lane<<2)
            const int pk = col * 128 | ((col & 31) << 2);
            #pragma unroll
            for (int a = 1; a <= 4; ++a) {
                const unsigned mm = __ballot_sync(0xffffffffu, act == a);
                int& d = (a == 1) ? d0 : (a == 2) ? d1 : (a == 3) ? d2 : d3;
                if (act == a) {
                    const int r = __popc(mm & ((1u << lane) - 1));
                    const float ww = (a == 4) ? 0.5f * w : w;   // sigmoid pre-halved
                    g_edges[d + r] = make_int2(pk, __float_as_int(ww));
                }
                d += __popc(mm);
            }
        }
    }
    __syncthreads();

    if (tid < NNODES) {
        const int n = tid;
        const bool hid = n < NH;
        const int cn = off[(n + 1) * 4] - off[n * 4];
        const int lo = hid ? 0 : NH, hi2 = hid ? NH : NNODES;
        int rank = 0;
        for (int j = lo; j < hi2; ++j) {
            const int cj = off[(j + 1) * 4] - off[j * 4];
            rank += (cj > cn) || (cj == cn && j < n);
        }
        const int r = rank >> 5;
        int wl = rank & 31;
        if (r & 1) wl = 31 - wl;
        const int slot = (hid ? 0 : NH) + r * 32 + wl;
        g_infoA[slot] = make_int4(off[n * 4], off[n * 4 + 1], off[n * 4 + 2], off[n * 4 + 3]);
        g_infoB[slot] = make_int2(off[(n + 1) * 4], hid ? n : n - NH);
    }
}

// ================= Main kernel ====================================================
#define EDGE_LOOP(E0, E1, BODY)                                              \
    _Pragma("unroll 4")                                                      \
    for (int e = (E0); e < (E1); ++e) {                                      \
        const int2 ed = __ldg(&g_edges[e]);                                  \
        const float s = *(const float*)(srcb + (ed.x ^ lane4));              \
        const float w = __int_as_float(ed.y);                                \
        BODY                                                                 \
    }

__global__ void __launch_bounds__(NTHREADS, 2)
wann_main(const float* __restrict__ x, float* __restrict__ out)
{
    extern __shared__ char sm[];
    float* src = (float*)sm;                         // [640*32] swizzled transposed
    float* buf = (float*)(sm + SRCW * TB * 4);       // [NO][33]

    const int tid = threadIdx.x, wid = tid >> 5, lane = tid & 31;
    const int lane4 = lane << 2;
    const char* srcb = (const char*)sm;
    const int b0t = blockIdx.x * TB;

    // ---- stage x tile: float2 loads, swizzled scalar stores (2-way conflicts) ----
    // 32 b-rows x 8 col-chunks(64) = 256 warp-iters / 32 warps = 8 each.
    #pragma unroll 1
    for (int it = wid; it < 256; it += NWARPS) {
        const int b = it >> 3;
        const int cch = it & 7;
        const int c = cch * 64 + lane * 2;
        const float2 v = *(const float2*)(x + (size_t)(b0t + b) * IN_DIM + c);
        const int q0 = (c)     * 128 + (((b ^ (c & 31)))       << 2);
        const int q1 = (c + 1) * 128 + (((b ^ ((c + 1) & 31))) << 2);
        *(float*)((char*)sm + q0) = v.x;
        *(float*)((char*)sm + q1) = v.y;
    }
    __syncthreads();

    // ---- hidden phase: warp = node (LPT), branch-free act segments ----
    #pragma unroll 1
    for (int rr = 0; rr < NH / NWARPS; ++rr) {
        const int slot = rr * NWARPS + wid;
        const int4 A  = __ldg(&g_infoA[slot]);
        const int2 Bi = __ldg(&g_infoB[slot]);
        float acc = 0.5f * (float)(Bi.x - A.w);      // folded sigmoid bias
        EDGE_LOOP(A.x, A.y, { acc = fmaf(w, s, acc); })
        EDGE_LOOP(A.y, A.z, { acc += tanha(w * s); })
        EDGE_LOOP(A.z, A.w, { acc += fmaxf(w * s, 0.f); })
        EDGE_LOOP(A.w, Bi.x, { acc = fmaf(0.5f, tanha(w * s), acc); })
        const int hc = IN_DIM + Bi.y;
        const int qh = hc * 128 | ((hc & 31) << 2);
        *(float*)((char*)sm + (qh ^ lane4)) = acc;
    }
    __syncthreads();

    // ---- output phase: warp = node, result straight into transpose buffer ----
    #pragma unroll 1
    for (int rr = 0; rr < NO / NWARPS; ++rr) {
        const int slot = NH + rr * NWARPS + wid;
        const int4 A  = __ldg(&g_infoA[slot]);
        const int2 Bi = __ldg(&g_infoB[slot]);
        float acc = 0.5f * (float)(Bi.x - A.w);
        EDGE_LOOP(A.x, A.y, { acc = fmaf(w, s, acc); })
        EDGE_LOOP(A.y, A.z, { acc += tanha(w * s); })
        EDGE_LOOP(A.z, A.w, { acc += fmaxf(w * s, 0.f); })
        EDGE_LOOP(A.w, Bi.x, { acc = fmaf(0.5f, tanha(w * s), acc); })
        buf[Bi.y * 33 + lane] = tanha(acc);
    }
    __syncthreads();

    // ---- write-out: warp = batch row, coalesced 128B stores ----
    #pragma unroll
    for (int ch = 0; ch < NO / 32; ++ch)
        out[(size_t)(b0t + wid) * NO + ch * 32 + lane] = buf[(ch * 32 + lane) * 33 + wid];
}

extern "C" void kernel_launch(void* const* d_in, const int* in_sizes, int n_in,
                              void* d_out, int out_size)
{
    const float* x      = (const float*)d_in[0];
    const float* wh     = (const float*)d_in[1];
    const float* wo     = (const float*)d_in[2];
    const int*   rows_h = (const int*)d_in[3];
    const int*   cols_h = (const int*)d_in[4];
    const int*   acts_h = (const int*)d_in[5];
    const int*   rows_o = (const int*)d_in[6];
    const int*   cols_o = (const int*)d_in[7];
    const int*   acts_o = (const int*)d_in[8];
    float* out = (float*)d_out;

    const int Eh = in_sizes[1];
    const int Eo = in_sizes[2];

    prep_all<<<1, 1024>>>(rows_h, cols_h, acts_h, wh,
                          rows_o, cols_o, acts_o, wo, Eh, Eo);

    const size_t smem = (size_t)SRCW * TB * 4      // src tile (80KB)
                      + (size_t)NO * 33 * 4;       // transpose buffer (33.8KB)
    cudaFuncSetAttribute(wann_main, cudaFuncAttributeMaxDynamicSharedMemorySize,
                         (int)smem);
    wann_main<<<BATCH / TB, NTHREADS, smem>>>(x, out);
}

// round 7
// speedup vs baseline: 1.4584x; 1.4584x over previous
#include <cuda_runtime.h>
#include <cuda_fp16.h>
#include <cstdint>

#define BATCH    16384
#define IN_DIM   512
#define NH       128
#define NO       256
#define NNODES   (NH + NO)         // 384
#define SRCW     (IN_DIM + NH)     // 640
#define TB       128               // batch rows per tile (4 per lane, fp16)
#define NTHREADS 1024
#define NWARPS   32
#define MAXE     16384

// src layout: col-major fp16, 256B per col. Element (col, b) at byte
//   col*256 + (((b>>2) ^ (col&31)) << 3) + (b&3)*2
// Lane l (batch 4l..4l+3) reads 8B at q ^ (l<<3), q = col*256 | ((col&31)<<3).

__device__ int2 g_edges[MAXE];       // packed (q, w), sorted by (node, act)
__device__ int4 g_infoA[NNODES];     // per schedule slot: e0,e1,e2,e3
__device__ int2 g_infoB[NNODES];     // per schedule slot: e4, node_id(local)

__device__ __forceinline__ float tanha(float z) {
    float r;
    asm("tanh.approx.f32 %0, %1;" : "=f"(r) : "f"(z));
    return r;
}

// ================= Fused prep: histogram + scan + scatter + LPT (1 block) =========
__global__ void __launch_bounds__(1024)
prep_all(const int* __restrict__ rows_h, const int* __restrict__ cols_h,
         const int* __restrict__ acts_h, const float* __restrict__ wh,
         const int* __restrict__ rows_o, const int* __restrict__ cols_o,
         const int* __restrict__ acts_o, const float* __restrict__ wo,
         int Eh, int Eo)
{
    __shared__ int cnt[NNODES * 4];
    __shared__ int off[NNODES * 4 + 1];
    __shared__ int wsum[32];

    const int tid = threadIdx.x, lane = tid & 31, wid = tid >> 5;

    for (int i = tid; i < NNODES * 4; i += 1024) cnt[i] = 0;
    __syncthreads();

    for (int e = tid; e < Eh; e += 1024)
        atomicAdd(&cnt[rows_h[e] * 4 + acts_h[e] - 1], 1);
    for (int e = tid; e < Eo; e += 1024)
        atomicAdd(&cnt[(NH + rows_o[e]) * 4 + acts_o[e] - 1], 1);
    __syncthreads();

    if (lane == 0) {
        const int base = wid * 48;
        int run = 0;
        for (int i = 0; i < 48; ++i) { off[base + i] = run; run += cnt[base + i]; }
        wsum[wid] = run;
    }
    __syncthreads();
    if (wid == 0) {
        const int v = wsum[lane];
        int ex = v;
        #pragma unroll
        for (int d = 1; d < 32; d <<= 1) {
            const int t = __shfl_up_sync(0xffffffffu, ex, d);
            if (lane >= d) ex += t;
        }
        ex -= v;
        wsum[lane] = ex;
        if (lane == 31) off[NNODES * 4] = ex + v;
    }
    __syncthreads();
    for (int i = tid; i < NNODES * 4; i += 1024) off[i] += wsum[i / 48];
    __syncthreads();

    for (int n = wid; n < NNODES; n += 32) {
        const bool hid = n < NH;
        const int* cols = hid ? cols_h : cols_o;
        const int* acts = hid ? acts_h : acts_o;
        const float* wp = hid ? wh : wo;
        const int sub = hid ? 0 : Eh;
        const int s = off[n * 4] - sub;
        const int e = off[(n + 1) * 4] - sub;
        int d0 = off[n * 4], d1 = off[n * 4 + 1], d2 = off[n * 4 + 2], d3 = off[n * 4 + 3];
        for (int c = s; c < e; c += 32) {
            const int idx = c + lane;
            const bool v = idx < e;
            const int act = v ? acts[idx] : 0;
            const int col = v ? cols[idx] : 0;
            const float w = v ? wp[idx] : 0.f;
            const int pk = col * 256 | ((col & 31) << 3);
            #pragma unroll
            for (int a = 1; a <= 4; ++a) {
                const unsigned mm = __ballot_sync(0xffffffffu, act == a);
                int& d = (a == 1) ? d0 : (a == 2) ? d1 : (a == 3) ? d2 : d3;
                if (act == a) {
                    const int r = __popc(mm & ((1u << lane) - 1));
                    const float ww = (a == 4) ? 0.5f * w : w;   // sigmoid pre-halved
                    g_edges[d + r] = make_int2(pk, __float_as_int(ww));
                }
                d += __popc(mm);
            }
        }
    }
    __syncthreads();

    // LPT schedules: hidden global over 128; output per-64-node chunk.
    if (tid < NNODES) {
        const int n = tid;
        const int cn = off[(n + 1) * 4] - off[n * 4];
        int slot, local;
        if (n < NH) {
            int rank = 0;
            for (int j = 0; j < NH; ++j) {
                const int cj = off[(j + 1) * 4] - off[j * 4];
                rank += (cj > cn) || (cj == cn && j < n);
            }
            const int r = rank >> 5;
            int wl = rank & 31;
            if (r & 1) wl = 31 - wl;
            slot = r * 32 + wl;
            local = n;
        } else {
            const int m = n - NH;                 // 0..255
            const int chunk = m >> 6;
            int rank = 0;
            for (int j = 0; j < 64; ++j) {
                const int jn = NH + chunk * 64 + j;
                const int cj = off[(jn + 1) * 4] - off[jn * 4];
                rank += (cj > cn) || (cj == cn && jn < n);
            }
            const int r = rank >> 5;              // 0 or 1
            int wl = rank & 31;
            if (r & 1) wl = 31 - wl;
            slot = NH + chunk * 64 + r * 32 + wl;
            local = m & 63;                       // position within chunk
        }
        g_infoA[slot] = make_int4(off[n * 4], off[n * 4 + 1], off[n * 4 + 2], off[n * 4 + 3]);
        g_infoB[slot] = make_int2(off[(n + 1) * 4], local);
    }
}

// ================= Main kernel ====================================================
#define EDGE_LOOP(E0, E1, BODY)                                              \
    _Pragma("unroll 4")                                                      \
    for (int e = (E0); e < (E1); ++e) {                                      \
        const int2 ed = __ldg(&g_edges[e]);                                  \
        const uint2 u = *(const uint2*)(srcb + (ed.x ^ lane8));              \
        const float2 f0 = __half22float2(*(const __half2*)&u.x);             \
        const float2 f1 = __half22float2(*(const __half2*)&u.y);             \
        const float w = __int_as_float(ed.y);                                \
        BODY                                                                 \
    }

__device__ __forceinline__ float4 node_accum(const char* __restrict__ srcb,
                                             int lane8, int4 A, int e4)
{
    const float bias = 0.5f * (float)(e4 - A.w);
    float4 a = make_float4(bias, bias, bias, bias);
    EDGE_LOOP(A.x, A.y, {                     // identity
        a.x = fmaf(w, f0.x, a.x); a.y = fmaf(w, f0.y, a.y);
        a.z = fmaf(w, f1.x, a.z); a.w = fmaf(w, f1.y, a.w); })
    EDGE_LOOP(A.y, A.z, {                     // tanh
        a.x += tanha(w * f0.x); a.y += tanha(w * f0.y);
        a.z += tanha(w * f1.x); a.w += tanha(w * f1.y); })
    EDGE_LOOP(A.z, A.w, {                     // relu
        a.x += fmaxf(w * f0.x, 0.f); a.y += fmaxf(w * f0.y, 0.f);
        a.z += fmaxf(w * f1.x, 0.f); a.w += fmaxf(w * f1.y, 0.f); })
    EDGE_LOOP(A.w, e4, {                      // sigmoid (w pre-halved, bias folded)
        a.x = fmaf(0.5f, tanha(w * f0.x), a.x); a.y = fmaf(0.5f, tanha(w * f0.y), a.y);
        a.z = fmaf(0.5f, tanha(w * f1.x), a.z); a.w = fmaf(0.5f, tanha(w * f1.y), a.w); })
    return a;
}

#define SRC_BYTES (SRCW * 256)               // 163840
#define BUFSTRIDE 132                        // floats per node row (16B-aligned, padded)

__global__ void __launch_bounds__(NTHREADS, 1)
wann_main(const float* __restrict__ x, float* __restrict__ out)
{
    extern __shared__ char sm[];
    char*  srcb = sm;                               // fp16 src tile, 160KB
    float* bufs = (float*)(sm + SRC_BYTES);         // [2][64][BUFSTRIDE]

    const int tid = threadIdx.x, wid = tid >> 5, lane = tid & 31;
    const int lane8 = lane << 3;
    const int b0t = blockIdx.x * TB;

    // ---- stage x tile: warp wid owns batch group wid (rows 4wid..4wid+3) ----
    {
        const size_t bb = (size_t)(b0t + wid * 4) * IN_DIM;
        #pragma unroll 4
        for (int k = 0; k < 16; ++k) {
            const int c = k * 32 + lane;
            const float v0 = x[bb + c];
            const float v1 = x[bb + IN_DIM + c];
            const float v2 = x[bb + 2 * IN_DIM + c];
            const float v3 = x[bb + 3 * IN_DIM + c];
            const __half2 ha = __floats2half2_rn(v0, v1);
            const __half2 hb = __floats2half2_rn(v2, v3);
            uint2 pv;
            pv.x = *(const unsigned*)&ha;
            pv.y = *(const unsigned*)&hb;
            // (c & 31) == lane here
            *(uint2*)(srcb + c * 256 + ((wid ^ lane) << 3)) = pv;
        }
    }
    __syncthreads();

    // ---- hidden phase: 4 rounds, warp = node (global LPT) ----
    #pragma unroll 1
    for (int rr = 0; rr < NH / NWARPS; ++rr) {
        const int slot = rr * NWARPS + wid;
        const int4 A  = __ldg(&g_infoA[slot]);
        const int2 Bi = __ldg(&g_infoB[slot]);
        const float4 a = node_accum(srcb, lane8, A, Bi.x);
        const __half2 ha = __floats2half2_rn(a.x, a.y);
        const __half2 hb = __floats2half2_rn(a.z, a.w);
        uint2 pv;
        pv.x = *(const unsigned*)&ha;
        pv.y = *(const unsigned*)&hb;
        const int hc = IN_DIM + Bi.y;
        const int qh = hc * 256 | ((hc & 31) << 3);
        *(uint2*)(srcb + (qh ^ lane8)) = pv;
    }
    __syncthreads();

    // ---- output: 4 rounds of one 64-node chunk each (LPT within chunk) ----
    #pragma unroll 1
    for (int r = 0; r < 4; ++r) {
        float* bp = bufs + (r & 1) * (64 * BUFSTRIDE);
        #pragma unroll
        for (int h = 0; h < 2; ++h) {
            const int slot = NH + r * 64 + h * 32 + wid;
            const int4 A  = __ldg(&g_infoA[slot]);
            const int2 Bi = __ldg(&g_infoB[slot]);
            const float4 a = node_accum(srcb, lane8, A, Bi.x);
            const float4 rv = make_float4(tanha(a.x), tanha(a.y), tanha(a.z), tanha(a.w));
            *(float4*)(bp + Bi.y * BUFSTRIDE + lane * 4) = rv;   // batches 4l..4l+3
        }
        __syncthreads();
        // readout: coalesced 128B stores; next round's STS targets other buffer.
        #pragma unroll
        for (int j = 0; j < 4; ++j) {
            const int b = j * 32 + wid;
            #pragma unroll
            for (int ch = 0; ch < 2; ++ch) {
                const int cc = ch * 32 + lane;
                out[(size_t)(b0t + b) * NO + r * 64 + cc] = bp[cc * BUFSTRIDE + b];
            }
        }
    }
}

extern "C" void kernel_launch(void* const* d_in, const int* in_sizes, int n_in,
                              void* d_out, int out_size)
{
    const float* x      = (const float*)d_in[0];
    const float* wh     = (const float*)d_in[1];
    const float* wo     = (const float*)d_in[2];
    const int*   rows_h = (const int*)d_in[3];
    const int*   cols_h = (const int*)d_in[4];
    const int*   acts_h = (const int*)d_in[5];
    const int*   rows_o = (const int*)d_in[6];
    const int*   cols_o = (const int*)d_in[7];
    const int*   acts_o = (const int*)d_in[8];
    float* out = (float*)d_out;

    const int Eh = in_sizes[1];
    const int Eo = in_sizes[2];

    prep_all<<<1, 1024>>>(rows_h, cols_h, acts_h, wh,
                          rows_o, cols_o, acts_o, wo, Eh, Eo);

    const size_t smem = (size_t)SRC_BYTES               // fp16 src tile
                      + (size_t)2 * 64 * BUFSTRIDE * 4; // double transpose buffer
    cudaFuncSetAttribute(wann_main, cudaFuncAttributeMaxDynamicSharedMemorySize,
                         (int)smem);
    wann_main<<<BATCH / TB, NTHREADS, smem>>>(x, out);
}